// round 11
// baseline (speedup 1.0000x reference)
#include <cuda_runtime.h>
#include <cuda_bf16.h>
#include <math.h>

// ---------------- problem constants ----------------
#define DIMC   96
#define HEADS  6
#define HD     16
#define PADW   2
#define DSP    24
#define NTOK   (24*24*24)
#define NWIN   27
#define QW3    512
#define KW3    1728
#define MLPH   192
#define NBLK2  (NWIN*HEADS*8)      // 1296 (w,h,64-query chunk) blocks
#define NTILE  54                  // 32-key tiles per window
#define LOG2E  1.44269504088896341f
#define QS     (0.25f * LOG2E)

// ---------------- scratch (bf16 tensors stored as packed u32 words) ----------------
__device__ __align__(256) unsigned g_xnh  [NTOK * 48];    // ln1 out   [tok][96]  bf16
__device__ __align__(256) unsigned g_qkvh [NTOK * 144];   // qkv out   [tok][288] bf16 (q pre-scaled)
__device__ __align__(256) unsigned g_attnh[NTOK * 48];    // attn out  [tok][96]  bf16
__device__ __align__(256) unsigned g_x2nh [NTOK * 48];    // ln2 out   [tok][96]  bf16
__device__ __align__(256) unsigned g_h1h  [NTOK * 96];    // gelu out  [tok][192] bf16
__device__ __align__(256) float    g_x2   [NTOK * DIMC];  // proj+res  f32
__device__ __align__(256) __nv_bfloat16 g_bias[(size_t)HEADS * QW3 * KW3]; // [h][q][k] *log2e
// K/V pre-gathered in mma fragment layout: [w][h][tile(54)][...256 u32 words...]
__device__ __align__(256) unsigned g_kf[(size_t)NWIN * HEADS * NTILE * 256];
__device__ __align__(256) unsigned g_vf[(size_t)NWIN * HEADS * NTILE * 256];
// weights in B-fragment layout: word[((ntG*KS + ks)*32 + lane)*2 + rh]
__device__ __align__(256) unsigned g_wqkv[36 * 6 * 64];   // 13824
__device__ __align__(256) unsigned g_wproj[12 * 6 * 64];  // 4608
__device__ __align__(256) unsigned g_wfc1[24 * 6 * 64];   // 9216
__device__ __align__(256) unsigned g_wfc2[12 * 12 * 64];  // 9216

// ---------------- asm helpers ----------------
__device__ __forceinline__ unsigned bfpack(float lo, float hi) {
    unsigned d; asm("cvt.rn.bf16x2.f32 %0, %1, %2;" : "=r"(d) : "f"(hi), "f"(lo)); return d;
}
__device__ __forceinline__ float ex2(float x) {
    float y; asm("ex2.approx.f32 %0, %1;" : "=f"(y) : "f"(x)); return y;
}
__device__ __forceinline__ void mma16816(float* d, const unsigned* a, unsigned b0, unsigned b1) {
    asm volatile("mma.sync.aligned.m16n8k16.row.col.f32.bf16.bf16.f32 "
        "{%0,%1,%2,%3}, {%4,%5,%6,%7}, {%8,%9}, {%0,%1,%2,%3};"
        : "+f"(d[0]), "+f"(d[1]), "+f"(d[2]), "+f"(d[3])
        : "r"(a[0]), "r"(a[1]), "r"(a[2]), "r"(a[3]), "r"(b0), "r"(b1));
}

// ---------------- LayerNorm (f32 in -> bf16 out) ----------------
__global__ void ln_kernel(const float* __restrict__ in,
                          const float* __restrict__ g,
                          const float* __restrict__ b,
                          __nv_bfloat16* __restrict__ out) {
    int t    = blockIdx.x * 8 + (threadIdx.x >> 5);
    int lane = threadIdx.x & 31;
    const float* row = in + (size_t)t * DIMC;
    float v0 = row[lane], v1 = row[lane + 32], v2 = row[lane + 64];
    float s  = v0 + v1 + v2;
    float sq = v0 * v0 + v1 * v1 + v2 * v2;
    #pragma unroll
    for (int o = 16; o; o >>= 1) {
        s  += __shfl_xor_sync(0xffffffffu, s,  o);
        sq += __shfl_xor_sync(0xffffffffu, sq, o);
    }
    float mean = s * (1.0f / DIMC);
    float var  = sq * (1.0f / DIMC) - mean * mean;
    float r    = rsqrtf(var + 1e-5f);
    __nv_bfloat16* orow = out + (size_t)t * DIMC;
    orow[lane]      = __float2bfloat16((v0 - mean) * r * g[lane]      + b[lane]);
    orow[lane + 32] = __float2bfloat16((v1 - mean) * r * g[lane + 32] + b[lane + 32]);
    orow[lane + 64] = __float2bfloat16((v2 - mean) * r * g[lane + 64] + b[lane + 64]);
}

// ---------------- fused prep: weight repack + bias gather ----------------
__global__ void prep_kernel(const float* __restrict__ qkv_w, const float* __restrict__ proj_w,
                            const float* __restrict__ fc1_w, const float* __restrict__ fc2_w,
                            const int* __restrict__ rpi, const float* __restrict__ rpb) {
    if (blockIdx.x < 144) {
        int id = blockIdx.x * 256 + threadIdx.x;
        const float* src; unsigned* dst; int CIN, KS, lid; bool qsc = false;
        if      (id < 13824)               { src = qkv_w;  dst = g_wqkv;  CIN = 96;  KS = 6;  lid = id;                 qsc = true; }
        else if (id < 13824 + 4608)        { src = proj_w; dst = g_wproj; CIN = 96;  KS = 6;  lid = id - 13824; }
        else if (id < 13824 + 4608 + 9216) { src = fc1_w;  dst = g_wfc1;  CIN = 96;  KS = 6;  lid = id - 13824 - 4608; }
        else                               { src = fc2_w;  dst = g_wfc2;  CIN = 192; KS = 12; lid = id - 13824 - 4608 - 9216; }
        int rh = lid & 1, lane = (lid >> 1) & 31;
        int rest = lid >> 6;
        int ks = rest % KS, ntG = rest / KS;
        int n = 8 * ntG + (lane >> 2);
        int k = 16 * ks + 8 * rh + 2 * (lane & 3);
        float w0 = src[(size_t)n * CIN + k], w1 = src[(size_t)n * CIN + k + 1];
        if (qsc && n < 96) { w0 *= QS; w1 *= QS; }   // fold attention q-scale into Wq
        dst[lid] = bfpack(w0, w1);
    } else {
        int i = (blockIdx.x - 144) * 256 + threadIdx.x;   // i = q*1728 + k
        if (i >= QW3 * KW3) return;
        int idx = rpi[i];
        int q = i / KW3, k = i - q * KW3;
        #pragma unroll
        for (int h = 0; h < HEADS; h++)
            g_bias[((size_t)h * QW3 + q) * KW3 + k] = __float2bfloat16(rpb[idx * HEADS + h] * LOG2E);
    }
}

// ---------------- GEMM epilogue ----------------
template <int COUT, int MODE>
__device__ __forceinline__ void gemm_store(float* acc, int ntG, int lj, int r0, int r1,
    const float* __restrict__ res, float* __restrict__ outf, unsigned* __restrict__ outh)
{
    int c0g = ntG * 8 + 2 * lj;
    if (MODE == 0) {
        outh[(size_t)r0 * (COUT / 2) + ntG * 4 + lj] = bfpack(acc[0], acc[1]);
        outh[(size_t)r1 * (COUT / 2) + ntG * 4 + lj] = bfpack(acc[2], acc[3]);
    } else if (MODE == 1) {
        float2 rv0 = *(const float2*)(res + (size_t)r0 * COUT + c0g);
        float2 rv1 = *(const float2*)(res + (size_t)r1 * COUT + c0g);
        *(float2*)(outf + (size_t)r0 * COUT + c0g) = make_float2(acc[0] + rv0.x, acc[1] + rv0.y);
        *(float2*)(outf + (size_t)r1 * COUT + c0g) = make_float2(acc[2] + rv1.x, acc[3] + rv1.y);
    } else {
        #pragma unroll
        for (int i = 0; i < 4; i++)
            acc[i] = 0.5f * acc[i] * (1.0f + erff(acc[i] * 0.70710678118654752f));
        outh[(size_t)r0 * (COUT / 2) + ntG * 4 + lj] = bfpack(acc[0], acc[1]);
        outh[(size_t)r1 * (COUT / 2) + ntG * 4 + lj] = bfpack(acc[2], acc[3]);
    }
}

// ---------------- mma GEMM: warp keeps A, sweeps NT n-tiles (fully unrolled) ----------------
// grid = (NTOK/64, COUT/(8*NT)). MODE: 0 = bf16 out, 1 = f32 out + res, 2 = gelu -> bf16
template <int CIN, int NT, int COUT, int MODE, bool QSC>
__global__ void __launch_bounds__(128) mma_gemm(
    const unsigned* __restrict__ A,
    const unsigned* __restrict__ wf,
    const float* __restrict__ bias,
    const float* __restrict__ res,
    float* __restrict__ outf,
    unsigned* __restrict__ outh)
{
    constexpr int KS = CIN / 16;
    int tid = threadIdx.x, lane = tid & 31, wp = tid >> 5;
    int lj = lane & 3, lr = lane >> 2;
    int t0 = blockIdx.x * 64 + wp * 16;
    int nt0 = blockIdx.y * NT;

    // A fragments: held in registers across the whole n sweep
    const unsigned* base0 = A + (size_t)(t0 + lr) * (CIN / 2) + lj;
    const unsigned* base1 = base0 + 8 * (CIN / 2);
    unsigned a[KS][4];
    #pragma unroll
    for (int ks = 0; ks < KS; ks++) {
        a[ks][0] = base0[8 * ks];     a[ks][1] = base1[8 * ks];
        a[ks][2] = base0[8 * ks + 4]; a[ks][3] = base1[8 * ks + 4];
    }

    const uint2* wfp = (const uint2*)wf + (size_t)(nt0 * KS) * 32 + lane;
    int r0 = t0 + lr, r1 = r0 + 8;

    #pragma unroll
    for (int nt = 0; nt < NT; nt += 2) {
        uint2 w0[KS], w1[KS];
        #pragma unroll
        for (int ks = 0; ks < KS; ks++) {
            w0[ks] = wfp[(nt * KS + ks) * 32];
            w1[ks] = wfp[((nt + 1) * KS + ks) * 32];
        }
        int ntG0 = nt0 + nt, ntG1 = nt0 + nt + 1;
        float acc0[4], acc1[4];
        {
            int cA = ntG0 * 8 + 2 * lj, cB = ntG1 * 8 + 2 * lj;
            float bA0 = bias[cA], bA1 = bias[cA + 1];
            float bB0 = bias[cB], bB1 = bias[cB + 1];
            if (QSC) {
                if (cA < 96) { bA0 *= QS; bA1 *= QS; }
                if (cB < 96) { bB0 *= QS; bB1 *= QS; }
            }
            acc0[0] = bA0; acc0[1] = bA1; acc0[2] = bA0; acc0[3] = bA1;
            acc1[0] = bB0; acc1[1] = bB1; acc1[2] = bB0; acc1[3] = bB1;
        }
        #pragma unroll
        for (int ks = 0; ks < KS; ks++) {
            mma16816(acc0, a[ks], w0[ks].x, w0[ks].y);
            mma16816(acc1, a[ks], w1[ks].x, w1[ks].y);
        }
        gemm_store<COUT, MODE>(acc0, ntG0, lj, r0, r1, res, outf, outh);
        gemm_store<COUT, MODE>(acc1, ntG1, lj, r0, r1, res, outf, outh);
    }
}

// ---------------- K/V pre-gather into fragment layout (pure word permutes) ----------------
__global__ void __launch_bounds__(384) kvprep_kernel() {
    int blk = blockIdx.x;
    int w = blk / NTILE, T = blk - w * NTILE;
    int wd = w / 9; int wr = w - wd * 9;
    int wh = wr / 3; int ww = wr - wh * 3;
    int tid = threadIdx.x;
    int isV = tid >= 192;
    int r = isV ? tid - 192 : tid;
    int j = r & 31, h = r >> 5;

    int kk = T * 32 + j;
    int kz = kk / 144; int r2 = kk - kz * 144;
    int ky = r2 / 12;  int kx = r2 - ky * 12;
    int gz = wd * 8 + kz - PADW, gy = wh * 8 + ky - PADW, gx = ww * 8 + kx - PADW;

    unsigned kw[8];
    if ((unsigned)gz < 24u && (unsigned)gy < 24u && (unsigned)gx < 24u) {
        const uint4* s = (const uint4*)(g_qkvh +
            (size_t)((gz * DSP + gy) * DSP + gx) * 144 + (isV ? 96 : 48) + h * 8);
        uint4 s0 = s[0], s1 = s[1];
        kw[0] = s0.x; kw[1] = s0.y; kw[2] = s0.z; kw[3] = s0.w;
        kw[4] = s1.x; kw[5] = s1.y; kw[6] = s1.z; kw[7] = s1.w;
    } else {
        #pragma unroll
        for (int i = 0; i < 8; i++) kw[i] = 0u;
    }

    size_t tilebase = ((size_t)(w * HEADS + h) * NTILE + T) * 256;
    if (!isV) {
        uint2* dst = (uint2*)(g_kf + tilebase);
        int nt = j >> 3, lgrp = 4 * (j & 7);
        #pragma unroll
        for (int d = 0; d < 4; d++)
            dst[nt * 32 + lgrp + d] = make_uint2(kw[d], kw[d + 4]);
    } else {
        // V: pair keys (even j, odd j). Word n of pair = {V[even][n], V[odd][n]}.
        unsigned* dst = g_vf + tilebase;
        int kc = j >> 4, k2 = j & 15;
        int slotj = (k2 >> 1) & 3, rh = k2 >> 3;
        int par = j & 1;
        #pragma unroll
        for (int i = 0; i < 8; i++) {
            unsigned p = __shfl_xor_sync(0xffffffffu, kw[i], 1);
            int n = 2 * i + par;
            unsigned word = par ? __byte_perm(p, kw[i], 0x7632)
                                : __byte_perm(kw[i], p, 0x5410);
            dst[((kc * 2 + (n >> 3)) * 32 + 4 * (n & 7) + slotj) * 2 + rh] = word;
        }
    }
}

// ---------------- attention helpers (two-stage software pipeline) ----------------
__device__ __forceinline__ void attn_load(
    const uint2* __restrict__ kG, const uint2* __restrict__ vG,
    const __nv_bfloat16* __restrict__ b0, const __nv_bfloat16* __restrict__ b1,
    int t, uint2* kb, uint2* vb, unsigned bb[2][4])
{
    const uint2* kN = kG + t * 128;
    const uint2* vN = vG + t * 128;
    #pragma unroll
    for (int nt = 0; nt < 4; nt++) { kb[nt] = kN[nt * 32]; vb[nt] = vN[nt * 32]; }
    #pragma unroll
    for (int nt = 0; nt < 4; nt++) {
        bb[0][nt] = *(const unsigned*)(b0 + t * 32 + nt * 8);
        bb[1][nt] = *(const unsigned*)(b1 + t * 32 + nt * 8);
    }
}

__device__ __forceinline__ void attn_tile(
    const uint2* kb, const uint2* vb, const unsigned bb[2][4],
    const unsigned* qfrag, float O[2][4], float* l)
{
    float S[4][4];
    #pragma unroll
    for (int nt = 0; nt < 4; nt++) {
        #pragma unroll
        for (int half = 0; half < 2; half++) {
            float2 bv = __bfloat1622float2(*(const __nv_bfloat162*)&bb[half][nt]);
            S[nt][2 * half]     = bv.x;
            S[nt][2 * half + 1] = bv.y;
        }
    }
    #pragma unroll
    for (int nt = 0; nt < 4; nt++)
        mma16816(S[nt], qfrag, kb[nt].x, kb[nt].y);

    unsigned pfrag[2][4];
    #pragma unroll
    for (int half = 0; half < 2; half++) {
        int c0 = 2 * half;
        float ls = 0.0f;
        #pragma unroll
        for (int nt = 0; nt < 4; nt++) {
            float p0 = ex2(S[nt][c0]);
            float p1 = ex2(S[nt][c0 + 1]);
            ls += p0 + p1;
            S[nt][c0] = p0; S[nt][c0 + 1] = p1;
        }
        l[half] += ls;
    }
    #pragma unroll
    for (int kc = 0; kc < 2; kc++) {
        pfrag[kc][0] = bfpack(S[2 * kc][0],     S[2 * kc][1]);
        pfrag[kc][1] = bfpack(S[2 * kc][2],     S[2 * kc][3]);
        pfrag[kc][2] = bfpack(S[2 * kc + 1][0], S[2 * kc + 1][1]);
        pfrag[kc][3] = bfpack(S[2 * kc + 1][2], S[2 * kc + 1][3]);
    }
    #pragma unroll
    for (int kc = 0; kc < 2; kc++)
        #pragma unroll
        for (int nt = 0; nt < 2; nt++)
            mma16816(O[nt], pfrag[kc], vb[kc * 2 + nt].x, vb[kc * 2 + nt].y);
}

// ---------------- attention: fixed-base softmax (m=0), barrier-free ----------------
__global__ void __launch_bounds__(128) attn_kernel() {
    int b   = blockIdx.x;                   // 0..1295
    int w   = b / 48;  int rem = b - w * 48;
    int h   = rem >> 3, qo = rem & 7;
    int wd  = w / 9;   int wr = w - wd * 9;
    int wh  = wr / 3;  int ww = wr - wh * 3;
    int tid = threadIdx.x;
    int lane = tid & 31, wp = tid >> 5;
    int lj = lane & 3, lr = lane >> 2;

    int qbase = qo * 64 + wp * 16;

    // ---- Q fragments: direct word loads (scale folded into Wq) + bias ptrs ----
    unsigned qfrag[4];
    const __nv_bfloat16* bp0;
    const __nv_bfloat16* bp1;
    int tqs[2];
    #pragma unroll
    for (int half = 0; half < 2; half++) {
        int qw = qbase + 8 * half + lr;
        int z = qw >> 6, y = (qw >> 3) & 7, xx = qw & 7;
        int tq = ((wd * 8 + z) * DSP + (wh * 8 + y)) * DSP + (ww * 8 + xx);
        tqs[half] = tq;
        const unsigned* qp = g_qkvh + (size_t)tq * 144 + h * 8 + lj;
        qfrag[half]     = qp[0];
        qfrag[2 + half] = qp[4];
        const __nv_bfloat16* bpp = g_bias + ((size_t)(h * QW3) + qw) * KW3 + 2 * lj;
        if (half == 0) bp0 = bpp; else bp1 = bpp;
    }

    const uint2* kG = (const uint2*)g_kf + ((size_t)(w * HEADS + h) * NTILE) * 128 + lane;
    const uint2* vG = (const uint2*)g_vf + ((size_t)(w * HEADS + h) * NTILE) * 128 + lane;

    float O[2][4];
    #pragma unroll
    for (int nt = 0; nt < 2; nt++)
        #pragma unroll
        for (int c = 0; c < 4; c++) O[nt][c] = 0.0f;
    float l[2] = { 0.0f, 0.0f };

    uint2 kbA[4], vbA[4], kbB[4], vbB[4];
    unsigned bbA[2][4], bbB[2][4];
    attn_load(kG, vG, bp0, bp1, 0, kbA, vbA, bbA);

    #pragma unroll 1
    for (int t = 0; t < NTILE; t += 2) {
        attn_load(kG, vG, bp0, bp1, t + 1, kbB, vbB, bbB);
        attn_tile(kbA, vbA, bbA, qfrag, O, l);
        int tn = (t + 2 < NTILE) ? t + 2 : NTILE - 1;   // clamped redundant load on last iter
        attn_load(kG, vG, bp0, bp1, tn, kbA, vbA, bbA);
        attn_tile(kbB, vbB, bbB, qfrag, O, l);
    }

    // ---- finalize: quad row-sum, normalize, write bf16 ----
    #pragma unroll
    for (int half = 0; half < 2; half++) {
        float ls = l[half];
        ls += __shfl_xor_sync(0xffffffffu, ls, 1);
        ls += __shfl_xor_sync(0xffffffffu, ls, 2);
        float inv = 1.0f / ls;
        int c0 = 2 * half;
        unsigned* row = g_attnh + (size_t)tqs[half] * 48 + h * 8 + lj;
        row[0] = bfpack(O[0][c0] * inv, O[0][c0 + 1] * inv);
        row[4] = bfpack(O[1][c0] * inv, O[1][c0 + 1] * inv);
    }
}

// ---------------- launch ----------------
extern "C" void kernel_launch(void* const* d_in, const int* in_sizes, int n_in,
                              void* d_out, int out_size) {
    const float* x      = (const float*)d_in[0];
    const float* ln1_w  = (const float*)d_in[1];
    const float* ln1_b  = (const float*)d_in[2];
    const float* qkv_w  = (const float*)d_in[3];
    const float* qkv_b  = (const float*)d_in[4];
    const float* rpb    = (const float*)d_in[5];
    const float* proj_w = (const float*)d_in[6];
    const float* proj_b = (const float*)d_in[7];
    const float* ln2_w  = (const float*)d_in[8];
    const float* ln2_b  = (const float*)d_in[9];
    const float* fc1_w  = (const float*)d_in[10];
    const float* fc1_b  = (const float*)d_in[11];
    const float* fc2_w  = (const float*)d_in[12];
    const float* fc2_b  = (const float*)d_in[13];
    const int*   rpi    = (const int*)  d_in[14];
    float* out = (float*)d_out;

    unsigned *xnh, *qkvh, *attnh, *x2nh, *h1h;
    unsigned *wqkv, *wproj, *wfc1, *wfc2;
    float* x2;
    cudaGetSymbolAddress((void**)&xnh,   g_xnh);
    cudaGetSymbolAddress((void**)&qkvh,  g_qkvh);
    cudaGetSymbolAddress((void**)&attnh, g_attnh);
    cudaGetSymbolAddress((void**)&x2nh,  g_x2nh);
    cudaGetSymbolAddress((void**)&h1h,   g_h1h);
    cudaGetSymbolAddress((void**)&x2,    g_x2);
    cudaGetSymbolAddress((void**)&wqkv,  g_wqkv);
    cudaGetSymbolAddress((void**)&wproj, g_wproj);
    cudaGetSymbolAddress((void**)&wfc1,  g_wfc1);
    cudaGetSymbolAddress((void**)&wfc2,  g_wfc2);

    prep_kernel<<<144 + (QW3 * KW3 + 255) / 256, 256>>>(qkv_w, proj_w, fc1_w, fc2_w, rpi, rpb);

    ln_kernel<<<NTOK / 8, 256>>>(x, ln1_w, ln1_b, (__nv_bfloat16*)xnh);
    mma_gemm<96, 12, 288, 0, true><<<dim3(NTOK / 64, 3), 128>>>(xnh, wqkv, qkv_b, nullptr, nullptr, qkvh);

    kvprep_kernel<<<NWIN * NTILE, 384>>>();
    attn_kernel<<<NBLK2, 128>>>();

    mma_gemm<96, 6, 96, 1, false><<<dim3(NTOK / 64, 2), 128>>>(attnh, wproj, proj_b, x, x2, nullptr);
    ln_kernel<<<NTOK / 8, 256>>>(x2, ln2_w, ln2_b, (__nv_bfloat16*)x2nh);
    mma_gemm<96, 12, 192, 2, false><<<dim3(NTOK / 64, 2), 128>>>(x2nh, wfc1, fc1_b, nullptr, nullptr, h1h);
    mma_gemm<192, 6, 96, 1, false><<<dim3(NTOK / 64, 2), 128>>>(h1h, wfc2, fc2_b, x2, out, nullptr);
}

// round 12
// speedup vs baseline: 1.0844x; 1.0844x over previous
#include <cuda_runtime.h>
#include <cuda_bf16.h>
#include <math.h>

// ---------------- problem constants ----------------
#define DIMC   96
#define HEADS  6
#define HD     16
#define PADW   2
#define DSP    24
#define NTOK   (24*24*24)
#define NWIN   27
#define QW3    512
#define KW3    1728
#define MLPH   192
#define NBLK2  (NWIN*HEADS*8)      // 1296 (w,h,64-query chunk) blocks
#define NTILE  54                  // 32-key tiles per window
#define LOG2E  1.44269504088896341f
#define QS     (0.25f * LOG2E)

// ---------------- scratch (bf16 tensors stored as packed u32 words) ----------------
__device__ __align__(256) unsigned g_xnh  [NTOK * 48];    // ln1 out   [tok][96]  bf16
__device__ __align__(256) unsigned g_qkvh [NTOK * 144];   // qkv out   [tok][288] bf16 (q pre-scaled)
__device__ __align__(256) unsigned g_attnh[NTOK * 48];    // attn out  [tok][96]  bf16
__device__ __align__(256) unsigned g_x2nh [NTOK * 48];    // ln2 out   [tok][96]  bf16
__device__ __align__(256) unsigned g_h1h  [NTOK * 96];    // gelu out  [tok][192] bf16
__device__ __align__(256) float    g_x2   [NTOK * DIMC];  // proj+res  f32
__device__ __align__(256) __nv_bfloat16 g_bias[(size_t)HEADS * QW3 * KW3]; // [h][q][k] *log2e
// K/V pre-gathered in mma fragment layout: [w][h][tile(54)][...256 u32 words...]
__device__ __align__(256) unsigned g_kf[(size_t)NWIN * HEADS * NTILE * 256];
__device__ __align__(256) unsigned g_vf[(size_t)NWIN * HEADS * NTILE * 256];
// weights in B-fragment layout: word[((ntG*KS + ks)*32 + lane)*2 + rh]
__device__ __align__(256) unsigned g_wqkv[36 * 6 * 64];   // 13824
__device__ __align__(256) unsigned g_wproj[12 * 6 * 64];  // 4608
__device__ __align__(256) unsigned g_wfc1[24 * 6 * 64];   // 9216
__device__ __align__(256) unsigned g_wfc2[12 * 12 * 64];  // 9216

// ---------------- asm helpers ----------------
__device__ __forceinline__ unsigned bfpack(float lo, float hi) {
    unsigned d; asm("cvt.rn.bf16x2.f32 %0, %1, %2;" : "=r"(d) : "f"(hi), "f"(lo)); return d;
}
__device__ __forceinline__ float ex2(float x) {
    float y; asm("ex2.approx.f32 %0, %1;" : "=f"(y) : "f"(x)); return y;
}
__device__ __forceinline__ void mma16816(float* d, const unsigned* a, unsigned b0, unsigned b1) {
    asm volatile("mma.sync.aligned.m16n8k16.row.col.f32.bf16.bf16.f32 "
        "{%0,%1,%2,%3}, {%4,%5,%6,%7}, {%8,%9}, {%0,%1,%2,%3};"
        : "+f"(d[0]), "+f"(d[1]), "+f"(d[2]), "+f"(d[3])
        : "r"(a[0]), "r"(a[1]), "r"(a[2]), "r"(a[3]), "r"(b0), "r"(b1));
}

// ---------------- LayerNorm (f32 in -> bf16 out) ----------------
__global__ void ln_kernel(const float* __restrict__ in,
                          const float* __restrict__ g,
                          const float* __restrict__ b,
                          __nv_bfloat16* __restrict__ out) {
    int t    = blockIdx.x * 8 + (threadIdx.x >> 5);
    int lane = threadIdx.x & 31;
    const float* row = in + (size_t)t * DIMC;
    float v0 = row[lane], v1 = row[lane + 32], v2 = row[lane + 64];
    float s  = v0 + v1 + v2;
    float sq = v0 * v0 + v1 * v1 + v2 * v2;
    #pragma unroll
    for (int o = 16; o; o >>= 1) {
        s  += __shfl_xor_sync(0xffffffffu, s,  o);
        sq += __shfl_xor_sync(0xffffffffu, sq, o);
    }
    float mean = s * (1.0f / DIMC);
    float var  = sq * (1.0f / DIMC) - mean * mean;
    float r    = rsqrtf(var + 1e-5f);
    __nv_bfloat16* orow = out + (size_t)t * DIMC;
    orow[lane]      = __float2bfloat16((v0 - mean) * r * g[lane]      + b[lane]);
    orow[lane + 32] = __float2bfloat16((v1 - mean) * r * g[lane + 32] + b[lane + 32]);
    orow[lane + 64] = __float2bfloat16((v2 - mean) * r * g[lane + 64] + b[lane + 64]);
}

// ---------------- fused prep: weight repack + bias gather ----------------
__global__ void prep_kernel(const float* __restrict__ qkv_w, const float* __restrict__ proj_w,
                            const float* __restrict__ fc1_w, const float* __restrict__ fc2_w,
                            const int* __restrict__ rpi, const float* __restrict__ rpb) {
    if (blockIdx.x < 144) {
        int id = blockIdx.x * 256 + threadIdx.x;
        const float* src; unsigned* dst; int CIN, KS, lid; bool qsc = false;
        if      (id < 13824)               { src = qkv_w;  dst = g_wqkv;  CIN = 96;  KS = 6;  lid = id;                 qsc = true; }
        else if (id < 13824 + 4608)        { src = proj_w; dst = g_wproj; CIN = 96;  KS = 6;  lid = id - 13824; }
        else if (id < 13824 + 4608 + 9216) { src = fc1_w;  dst = g_wfc1;  CIN = 96;  KS = 6;  lid = id - 13824 - 4608; }
        else                               { src = fc2_w;  dst = g_wfc2;  CIN = 192; KS = 12; lid = id - 13824 - 4608 - 9216; }
        int rh = lid & 1, lane = (lid >> 1) & 31;
        int rest = lid >> 6;
        int ks = rest % KS, ntG = rest / KS;
        int n = 8 * ntG + (lane >> 2);
        int k = 16 * ks + 8 * rh + 2 * (lane & 3);
        float w0 = src[(size_t)n * CIN + k], w1 = src[(size_t)n * CIN + k + 1];
        if (qsc && n < 96) { w0 *= QS; w1 *= QS; }   // fold attention q-scale into Wq
        dst[lid] = bfpack(w0, w1);
    } else {
        int i = (blockIdx.x - 144) * 256 + threadIdx.x;   // i = q*1728 + k
        if (i >= QW3 * KW3) return;
        int idx = rpi[i];
        int q = i / KW3, k = i - q * KW3;
        #pragma unroll
        for (int h = 0; h < HEADS; h++)
            g_bias[((size_t)h * QW3 + q) * KW3 + k] = __float2bfloat16(rpb[idx * HEADS + h] * LOG2E);
    }
}

// ---------------- mma GEMM (R10 config): 2 n-tiles per block, weights prefetched ----------------
// grid = (NTOK/64, COUT/16). MODE: 0 = bf16 out, 1 = f32 out + res, 2 = gelu -> bf16
template <int CIN, int MODE, bool QSC>
__global__ void __launch_bounds__(128) mma_gemm(
    const unsigned* __restrict__ A,
    const unsigned* __restrict__ wf,
    const float* __restrict__ bias,
    const float* __restrict__ res,
    float* __restrict__ outf,
    unsigned* __restrict__ outh,
    int COUT)
{
    constexpr int KS = CIN / 16;
    int tid = threadIdx.x, lane = tid & 31, wp = tid >> 5;
    int lj = lane & 3, lr = lane >> 2;
    int t0 = blockIdx.x * 64 + wp * 16;
    int ntG0 = blockIdx.y * 2;

    // prefetch both n-tiles' weights (independent MLP burst)
    uint2 bw[2][KS];
    #pragma unroll
    for (int nt = 0; nt < 2; nt++) {
        const uint2* wfp = (const uint2*)wf + (size_t)((ntG0 + nt) * KS) * 32 + lane;
        #pragma unroll
        for (int ks = 0; ks < KS; ks++) bw[nt][ks] = wfp[ks * 32];
    }

    // A fragments
    const unsigned* base0 = A + (size_t)(t0 + lr) * (CIN / 2) + lj;
    const unsigned* base1 = base0 + 8 * (CIN / 2);
    unsigned a[KS][4];
    #pragma unroll
    for (int ks = 0; ks < KS; ks++) {
        a[ks][0] = base0[8 * ks];     a[ks][1] = base1[8 * ks];
        a[ks][2] = base0[8 * ks + 4]; a[ks][3] = base1[8 * ks + 4];
    }

    float acc[2][4];
    #pragma unroll
    for (int nt = 0; nt < 2; nt++) {
        int c0g = (ntG0 + nt) * 8 + 2 * lj;
        float bv0 = bias[c0g], bv1 = bias[c0g + 1];
        if (QSC && c0g < 96) { bv0 *= QS; bv1 *= QS; }
        acc[nt][0] = bv0; acc[nt][1] = bv1; acc[nt][2] = bv0; acc[nt][3] = bv1;
    }
    // two independent accumulator chains, interleaved
    #pragma unroll
    for (int ks = 0; ks < KS; ks++) {
        mma16816(acc[0], a[ks], bw[0][ks].x, bw[0][ks].y);
        mma16816(acc[1], a[ks], bw[1][ks].x, bw[1][ks].y);
    }

    int r0 = t0 + lr, r1 = r0 + 8;
    #pragma unroll
    for (int nt = 0; nt < 2; nt++) {
        int ntG = ntG0 + nt;
        int c0g = ntG * 8 + 2 * lj;
        if (MODE == 0) {
            outh[(size_t)r0 * (COUT / 2) + ntG * 4 + lj] = bfpack(acc[nt][0], acc[nt][1]);
            outh[(size_t)r1 * (COUT / 2) + ntG * 4 + lj] = bfpack(acc[nt][2], acc[nt][3]);
        } else if (MODE == 1) {
            float2 rv0 = *(const float2*)(res + (size_t)r0 * COUT + c0g);
            float2 rv1 = *(const float2*)(res + (size_t)r1 * COUT + c0g);
            *(float2*)(outf + (size_t)r0 * COUT + c0g) = make_float2(acc[nt][0] + rv0.x, acc[nt][1] + rv0.y);
            *(float2*)(outf + (size_t)r1 * COUT + c0g) = make_float2(acc[nt][2] + rv1.x, acc[nt][3] + rv1.y);
        } else {
            #pragma unroll
            for (int i = 0; i < 4; i++)
                acc[nt][i] = 0.5f * acc[nt][i] * (1.0f + erff(acc[nt][i] * 0.70710678118654752f));
            outh[(size_t)r0 * (COUT / 2) + ntG * 4 + lj] = bfpack(acc[nt][0], acc[nt][1]);
            outh[(size_t)r1 * (COUT / 2) + ntG * 4 + lj] = bfpack(acc[nt][2], acc[nt][3]);
        }
    }
}

// ---------------- K/V pre-gather into fragment layout (pure word permutes) ----------------
__global__ void __launch_bounds__(384) kvprep_kernel() {
    int blk = blockIdx.x;
    int w = blk / NTILE, T = blk - w * NTILE;
    int wd = w / 9; int wr = w - wd * 9;
    int wh = wr / 3; int ww = wr - wh * 3;
    int tid = threadIdx.x;
    int isV = tid >= 192;
    int r = isV ? tid - 192 : tid;
    int j = r & 31, h = r >> 5;

    int kk = T * 32 + j;
    int kz = kk / 144; int r2 = kk - kz * 144;
    int ky = r2 / 12;  int kx = r2 - ky * 12;
    int gz = wd * 8 + kz - PADW, gy = wh * 8 + ky - PADW, gx = ww * 8 + kx - PADW;

    unsigned kw[8];
    if ((unsigned)gz < 24u && (unsigned)gy < 24u && (unsigned)gx < 24u) {
        const uint4* s = (const uint4*)(g_qkvh +
            (size_t)((gz * DSP + gy) * DSP + gx) * 144 + (isV ? 96 : 48) + h * 8);
        uint4 s0 = s[0], s1 = s[1];
        kw[0] = s0.x; kw[1] = s0.y; kw[2] = s0.z; kw[3] = s0.w;
        kw[4] = s1.x; kw[5] = s1.y; kw[6] = s1.z; kw[7] = s1.w;
    } else {
        #pragma unroll
        for (int i = 0; i < 8; i++) kw[i] = 0u;
    }

    size_t tilebase = ((size_t)(w * HEADS + h) * NTILE + T) * 256;
    if (!isV) {
        uint2* dst = (uint2*)(g_kf + tilebase);
        int nt = j >> 3, lgrp = 4 * (j & 7);
        #pragma unroll
        for (int d = 0; d < 4; d++)
            dst[nt * 32 + lgrp + d] = make_uint2(kw[d], kw[d + 4]);
    } else {
        // V: pair keys (even j, odd j). Word n of pair = {V[even][n], V[odd][n]}.
        unsigned* dst = g_vf + tilebase;
        int kc = j >> 4, k2 = j & 15;
        int slotj = (k2 >> 1) & 3, rh = k2 >> 3;
        int par = j & 1;
        #pragma unroll
        for (int i = 0; i < 8; i++) {
            unsigned p = __shfl_xor_sync(0xffffffffu, kw[i], 1);
            int n = 2 * i + par;
            unsigned word = par ? __byte_perm(p, kw[i], 0x7632)
                                : __byte_perm(kw[i], p, 0x5410);
            dst[((kc * 2 + (n >> 3)) * 32 + 4 * (n & 7) + slotj) * 2 + rh] = word;
        }
    }
}

// ---------------- attention: fixed-base softmax (m=0), barrier-free (R10 loop) ----------------
__global__ void __launch_bounds__(128) attn_kernel() {
    int b   = blockIdx.x;                   // 0..1295
    int w   = b / 48;  int rem = b - w * 48;
    int h   = rem >> 3, qo = rem & 7;
    int wd  = w / 9;   int wr = w - wd * 9;
    int wh  = wr / 3;  int ww = wr - wh * 3;
    int tid = threadIdx.x;
    int lane = tid & 31, wp = tid >> 5;
    int lj = lane & 3, lr = lane >> 2;

    int qbase = qo * 64 + wp * 16;

    // ---- Q fragments: direct word loads (scale folded into Wq) + bias ptrs ----
    unsigned qfrag[4];
    const __nv_bfloat16* bp[2];
    int tqs[2];
    #pragma unroll
    for (int half = 0; half < 2; half++) {
        int qw = qbase + 8 * half + lr;
        int z = qw >> 6, y = (qw >> 3) & 7, xx = qw & 7;
        int tq = ((wd * 8 + z) * DSP + (wh * 8 + y)) * DSP + (ww * 8 + xx);
        tqs[half] = tq;
        const unsigned* qp = g_qkvh + (size_t)tq * 144 + h * 8 + lj;
        qfrag[half]     = qp[0];
        qfrag[2 + half] = qp[4];
        bp[half] = g_bias + ((size_t)(h * QW3) + qw) * KW3 + 2 * lj;
    }

    const uint2* kG = (const uint2*)g_kf + ((size_t)(w * HEADS + h) * NTILE) * 128 + lane;
    const uint2* vG = (const uint2*)g_vf + ((size_t)(w * HEADS + h) * NTILE) * 128 + lane;

    float O[2][4];
    #pragma unroll
    for (int nt = 0; nt < 2; nt++)
        #pragma unroll
        for (int c = 0; c < 4; c++) O[nt][c] = 0.0f;
    float l[2] = { 0.0f, 0.0f };

    uint2 kb[4], vb[4], kbn[4], vbn[4];
    unsigned bb[2][4], bbn[2][4];
    #pragma unroll
    for (int nt = 0; nt < 4; nt++) { kb[nt] = kG[nt * 32]; vb[nt] = vG[nt * 32]; }
    #pragma unroll
    for (int half = 0; half < 2; half++)
        #pragma unroll
        for (int nt = 0; nt < 4; nt++)
            bb[half][nt] = *(const unsigned*)(bp[half] + nt * 8);

    #pragma unroll 2
    for (int t = 0; t < NTILE; t++) {
        if (t + 1 < NTILE) {
            const uint2* kN = kG + (t + 1) * 128;
            const uint2* vN = vG + (t + 1) * 128;
            #pragma unroll
            for (int nt = 0; nt < 4; nt++) { kbn[nt] = kN[nt * 32]; vbn[nt] = vN[nt * 32]; }
            #pragma unroll
            for (int half = 0; half < 2; half++)
                #pragma unroll
                for (int nt = 0; nt < 4; nt++)
                    bbn[half][nt] = *(const unsigned*)(bp[half] + (t + 1) * 32 + nt * 8);
        }

        // ---- S = bias; S += Q K^T ----
        float S[4][4];
        #pragma unroll
        for (int nt = 0; nt < 4; nt++) {
            #pragma unroll
            for (int half = 0; half < 2; half++) {
                float2 bv = __bfloat1622float2(*(const __nv_bfloat162*)&bb[half][nt]);
                S[nt][2 * half]     = bv.x;
                S[nt][2 * half + 1] = bv.y;
            }
        }
        #pragma unroll
        for (int nt = 0; nt < 4; nt++)
            mma16816(S[nt], qfrag, kb[nt].x, kb[nt].y);

        // ---- p = exp2(s), fixed base ----
        unsigned pfrag[2][4];
        #pragma unroll
        for (int half = 0; half < 2; half++) {
            int c0 = 2 * half;
            float ls = 0.0f;
            #pragma unroll
            for (int nt = 0; nt < 4; nt++) {
                float p0 = ex2(S[nt][c0]);
                float p1 = ex2(S[nt][c0 + 1]);
                ls += p0 + p1;
                S[nt][c0] = p0; S[nt][c0 + 1] = p1;
            }
            l[half] += ls;
        }
        #pragma unroll
        for (int kc = 0; kc < 2; kc++) {
            pfrag[kc][0] = bfpack(S[2 * kc][0],     S[2 * kc][1]);
            pfrag[kc][1] = bfpack(S[2 * kc][2],     S[2 * kc][3]);
            pfrag[kc][2] = bfpack(S[2 * kc + 1][0], S[2 * kc + 1][1]);
            pfrag[kc][3] = bfpack(S[2 * kc + 1][2], S[2 * kc + 1][3]);
        }

        // ---- O += P V ----
        #pragma unroll
        for (int kc = 0; kc < 2; kc++)
            #pragma unroll
            for (int nt = 0; nt < 2; nt++)
                mma16816(O[nt], pfrag[kc], vb[kc * 2 + nt].x, vb[kc * 2 + nt].y);

        #pragma unroll
        for (int nt = 0; nt < 4; nt++) { kb[nt] = kbn[nt]; vb[nt] = vbn[nt]; }
        #pragma unroll
        for (int half = 0; half < 2; half++)
            #pragma unroll
            for (int nt = 0; nt < 4; nt++) bb[half][nt] = bbn[half][nt];
    }

    // ---- finalize: quad row-sum, normalize, write bf16 ----
    #pragma unroll
    for (int half = 0; half < 2; half++) {
        float ls = l[half];
        ls += __shfl_xor_sync(0xffffffffu, ls, 1);
        ls += __shfl_xor_sync(0xffffffffu, ls, 2);
        float inv = 1.0f / ls;
        int c0 = 2 * half;
        unsigned* row = g_attnh + (size_t)tqs[half] * 48 + h * 8 + lj;
        row[0] = bfpack(O[0][c0] * inv, O[0][c0 + 1] * inv);
        row[4] = bfpack(O[1][c0] * inv, O[1][c0 + 1] * inv);
    }
}

// ---------------- launch ----------------
extern "C" void kernel_launch(void* const* d_in, const int* in_sizes, int n_in,
                              void* d_out, int out_size) {
    const float* x      = (const float*)d_in[0];
    const float* ln1_w  = (const float*)d_in[1];
    const float* ln1_b  = (const float*)d_in[2];
    const float* qkv_w  = (const float*)d_in[3];
    const float* qkv_b  = (const float*)d_in[4];
    const float* rpb    = (const float*)d_in[5];
    const float* proj_w = (const float*)d_in[6];
    const float* proj_b = (const float*)d_in[7];
    const float* ln2_w  = (const float*)d_in[8];
    const float* ln2_b  = (const float*)d_in[9];
    const float* fc1_w  = (const float*)d_in[10];
    const float* fc1_b  = (const float*)d_in[11];
    const float* fc2_w  = (const float*)d_in[12];
    const float* fc2_b  = (const float*)d_in[13];
    const int*   rpi    = (const int*)  d_in[14];
    float* out = (float*)d_out;

    unsigned *xnh, *qkvh, *attnh, *x2nh, *h1h;
    unsigned *wqkv, *wproj, *wfc1, *wfc2;
    float* x2;
    cudaGetSymbolAddress((void**)&xnh,   g_xnh);
    cudaGetSymbolAddress((void**)&qkvh,  g_qkvh);
    cudaGetSymbolAddress((void**)&attnh, g_attnh);
    cudaGetSymbolAddress((void**)&x2nh,  g_x2nh);
    cudaGetSymbolAddress((void**)&h1h,   g_h1h);
    cudaGetSymbolAddress((void**)&x2,    g_x2);
    cudaGetSymbolAddress((void**)&wqkv,  g_wqkv);
    cudaGetSymbolAddress((void**)&wproj, g_wproj);
    cudaGetSymbolAddress((void**)&wfc1,  g_wfc1);
    cudaGetSymbolAddress((void**)&wfc2,  g_wfc2);

    prep_kernel<<<144 + (QW3 * KW3 + 255) / 256, 256>>>(qkv_w, proj_w, fc1_w, fc2_w, rpi, rpb);

    ln_kernel<<<NTOK / 8, 256>>>(x, ln1_w, ln1_b, (__nv_bfloat16*)xnh);
    mma_gemm<96, 0, true><<<dim3(NTOK / 64, 18), 128>>>(xnh, wqkv, qkv_b, nullptr, nullptr, qkvh, 288);

    kvprep_kernel<<<NWIN * NTILE, 384>>>();
    attn_kernel<<<NBLK2, 128>>>();

    mma_gemm<96, 1, false><<<dim3(NTOK / 64, 6), 128>>>(attnh, wproj, proj_b, x, x2, nullptr, 96);
    ln_kernel<<<NTOK / 8, 256>>>(x2, ln2_w, ln2_b, (__nv_bfloat16*)x2nh);
    mma_gemm<96, 2, false><<<dim3(NTOK / 64, 12), 128>>>(x2nh, wfc1, fc1_b, nullptr, nullptr, h1h, 192);
    mma_gemm<192, 1, false><<<dim3(NTOK / 64, 6), 128>>>(h1h, wfc2, fc2_b, x2, out, nullptr, 96);
}

// round 13
// speedup vs baseline: 1.0876x; 1.0030x over previous
#include <cuda_runtime.h>
#include <cuda_bf16.h>
#include <math.h>

// ---------------- problem constants ----------------
#define DIMC   96
#define HEADS  6
#define HD     16
#define PADW   2
#define DSP    24
#define NTOK   (24*24*24)
#define NWIN   27
#define QW3    512
#define KW3    1728
#define MLPH   192
#define NBLK2  (NWIN*HEADS*8)      // 1296 (w,h,64-query chunk) blocks
#define NTILE  54                  // 32-key tiles per window
#define LOG2E  1.44269504088896341f
#define QS     (0.25f * LOG2E)

// ---------------- scratch (bf16 tensors stored as packed u32 words) ----------------
__device__ __align__(256) unsigned g_xnh  [NTOK * 48];    // ln1 out   [tok][96]  bf16
__device__ __align__(256) unsigned g_qkvh [NTOK * 144];   // qkv out   [tok][288] bf16 (q pre-scaled)
__device__ __align__(256) unsigned g_attnh[NTOK * 48];    // attn out  [tok][96]  bf16
__device__ __align__(256) unsigned g_x2nh [NTOK * 48];    // ln2 out   [tok][96]  bf16
__device__ __align__(256) unsigned g_h1h  [NTOK * 96];    // gelu out  [tok][192] bf16
__device__ __align__(256) float    g_x2   [NTOK * DIMC];  // proj+res  f32
__device__ __align__(256) __nv_bfloat16 g_bias[(size_t)HEADS * QW3 * KW3]; // [h][q][k] *log2e
// K/V pre-gathered in mma fragment layout: [w][h][tile(54)][...256 u32 words...]
__device__ __align__(256) unsigned g_kf[(size_t)NWIN * HEADS * NTILE * 256];
__device__ __align__(256) unsigned g_vf[(size_t)NWIN * HEADS * NTILE * 256];
// weights in B-fragment layout: word[((ntG*KS + ks)*32 + lane)*2 + rh]
__device__ __align__(256) unsigned g_wqkv[36 * 6 * 64];   // 13824
__device__ __align__(256) unsigned g_wproj[12 * 6 * 64];  // 4608
__device__ __align__(256) unsigned g_wfc1[24 * 6 * 64];   // 9216
__device__ __align__(256) unsigned g_wfc2[12 * 12 * 64];  // 9216

// ---------------- asm helpers ----------------
__device__ __forceinline__ unsigned bfpack(float lo, float hi) {
    unsigned d; asm("cvt.rn.bf16x2.f32 %0, %1, %2;" : "=r"(d) : "f"(hi), "f"(lo)); return d;
}
__device__ __forceinline__ float ex2(float x) {
    float y; asm("ex2.approx.f32 %0, %1;" : "=f"(y) : "f"(x)); return y;
}
__device__ __forceinline__ void mma16816(float* d, const unsigned* a, unsigned b0, unsigned b1) {
    asm volatile("mma.sync.aligned.m16n8k16.row.col.f32.bf16.bf16.f32 "
        "{%0,%1,%2,%3}, {%4,%5,%6,%7}, {%8,%9}, {%0,%1,%2,%3};"
        : "+f"(d[0]), "+f"(d[1]), "+f"(d[2]), "+f"(d[3])
        : "r"(a[0]), "r"(a[1]), "r"(a[2]), "r"(a[3]), "r"(b0), "r"(b1));
}
// bf16x2 word -> two f32 via bit shifts (exact; ALU pipe, not cvt/XU)
__device__ __forceinline__ void bf2x_unpack(unsigned w, float& lo, float& hi) {
    lo = __uint_as_float(w << 16);
    hi = __uint_as_float(w & 0xffff0000u);
}

// ---------------- LayerNorm (f32 in -> bf16 out) ----------------
__global__ void ln_kernel(const float* __restrict__ in,
                          const float* __restrict__ g,
                          const float* __restrict__ b,
                          __nv_bfloat16* __restrict__ out) {
    int t    = blockIdx.x * 8 + (threadIdx.x >> 5);
    int lane = threadIdx.x & 31;
    const float* row = in + (size_t)t * DIMC;
    float v0 = row[lane], v1 = row[lane + 32], v2 = row[lane + 64];
    float s  = v0 + v1 + v2;
    float sq = v0 * v0 + v1 * v1 + v2 * v2;
    #pragma unroll
    for (int o = 16; o; o >>= 1) {
        s  += __shfl_xor_sync(0xffffffffu, s,  o);
        sq += __shfl_xor_sync(0xffffffffu, sq, o);
    }
    float mean = s * (1.0f / DIMC);
    float var  = sq * (1.0f / DIMC) - mean * mean;
    float r    = rsqrtf(var + 1e-5f);
    __nv_bfloat16* orow = out + (size_t)t * DIMC;
    orow[lane]      = __float2bfloat16((v0 - mean) * r * g[lane]      + b[lane]);
    orow[lane + 32] = __float2bfloat16((v1 - mean) * r * g[lane + 32] + b[lane + 32]);
    orow[lane + 64] = __float2bfloat16((v2 - mean) * r * g[lane + 64] + b[lane + 64]);
}

// ---------------- fused prep: weight repack + bias gather ----------------
__global__ void prep_kernel(const float* __restrict__ qkv_w, const float* __restrict__ proj_w,
                            const float* __restrict__ fc1_w, const float* __restrict__ fc2_w,
                            const int* __restrict__ rpi, const float* __restrict__ rpb) {
    if (blockIdx.x < 144) {
        int id = blockIdx.x * 256 + threadIdx.x;
        const float* src; unsigned* dst; int CIN, KS, lid; bool qsc = false;
        if      (id < 13824)               { src = qkv_w;  dst = g_wqkv;  CIN = 96;  KS = 6;  lid = id;                 qsc = true; }
        else if (id < 13824 + 4608)        { src = proj_w; dst = g_wproj; CIN = 96;  KS = 6;  lid = id - 13824; }
        else if (id < 13824 + 4608 + 9216) { src = fc1_w;  dst = g_wfc1;  CIN = 96;  KS = 6;  lid = id - 13824 - 4608; }
        else                               { src = fc2_w;  dst = g_wfc2;  CIN = 192; KS = 12; lid = id - 13824 - 4608 - 9216; }
        int rh = lid & 1, lane = (lid >> 1) & 31;
        int rest = lid >> 6;
        int ks = rest % KS, ntG = rest / KS;
        int n = 8 * ntG + (lane >> 2);
        int k = 16 * ks + 8 * rh + 2 * (lane & 3);
        float w0 = src[(size_t)n * CIN + k], w1 = src[(size_t)n * CIN + k + 1];
        if (qsc && n < 96) { w0 *= QS; w1 *= QS; }   // fold attention q-scale into Wq
        dst[lid] = bfpack(w0, w1);
    } else {
        int i = (blockIdx.x - 144) * 256 + threadIdx.x;   // i = q*1728 + k
        if (i >= QW3 * KW3) return;
        int idx = rpi[i];
        int q = i / KW3, k = i - q * KW3;
        #pragma unroll
        for (int h = 0; h < HEADS; h++)
            g_bias[((size_t)h * QW3 + q) * KW3 + k] = __float2bfloat16(rpb[idx * HEADS + h] * LOG2E);
    }
}

// ---------------- mma GEMM: NT n-tiles per block, all weights prefetched ----------------
// grid = (NTOK/64, COUT/(8*NT)). MODE: 0 = bf16 out, 1 = f32 out + res, 2 = gelu -> bf16
template <int CIN, int NT, int MODE, bool QSC>
__global__ void __launch_bounds__(128) mma_gemm(
    const unsigned* __restrict__ A,
    const unsigned* __restrict__ wf,
    const float* __restrict__ bias,
    const float* __restrict__ res,
    float* __restrict__ outf,
    unsigned* __restrict__ outh,
    int COUT)
{
    constexpr int KS = CIN / 16;
    int tid = threadIdx.x, lane = tid & 31, wp = tid >> 5;
    int lj = lane & 3, lr = lane >> 2;
    int t0 = blockIdx.x * 64 + wp * 16;
    int ntG0 = blockIdx.y * NT;

    // prefetch all NT n-tiles' weights (independent MLP burst)
    uint2 bw[NT][KS];
    #pragma unroll
    for (int nt = 0; nt < NT; nt++) {
        const uint2* wfp = (const uint2*)wf + (size_t)((ntG0 + nt) * KS) * 32 + lane;
        #pragma unroll
        for (int ks = 0; ks < KS; ks++) bw[nt][ks] = wfp[ks * 32];
    }

    // A fragments
    const unsigned* base0 = A + (size_t)(t0 + lr) * (CIN / 2) + lj;
    const unsigned* base1 = base0 + 8 * (CIN / 2);
    unsigned a[KS][4];
    #pragma unroll
    for (int ks = 0; ks < KS; ks++) {
        a[ks][0] = base0[8 * ks];     a[ks][1] = base1[8 * ks];
        a[ks][2] = base0[8 * ks + 4]; a[ks][3] = base1[8 * ks + 4];
    }

    float acc[NT][4];
    #pragma unroll
    for (int nt = 0; nt < NT; nt++) {
        int c0g = (ntG0 + nt) * 8 + 2 * lj;
        float bv0 = bias[c0g], bv1 = bias[c0g + 1];
        if (QSC && c0g < 96) { bv0 *= QS; bv1 *= QS; }
        acc[nt][0] = bv0; acc[nt][1] = bv1; acc[nt][2] = bv0; acc[nt][3] = bv1;
    }
    // NT independent accumulator chains, interleaved
    #pragma unroll
    for (int ks = 0; ks < KS; ks++)
        #pragma unroll
        for (int nt = 0; nt < NT; nt++)
            mma16816(acc[nt], a[ks], bw[nt][ks].x, bw[nt][ks].y);

    int r0 = t0 + lr, r1 = r0 + 8;
    #pragma unroll
    for (int nt = 0; nt < NT; nt++) {
        int ntG = ntG0 + nt;
        int c0g = ntG * 8 + 2 * lj;
        if (MODE == 0) {
            outh[(size_t)r0 * (COUT / 2) + ntG * 4 + lj] = bfpack(acc[nt][0], acc[nt][1]);
            outh[(size_t)r1 * (COUT / 2) + ntG * 4 + lj] = bfpack(acc[nt][2], acc[nt][3]);
        } else if (MODE == 1) {
            float2 rv0 = *(const float2*)(res + (size_t)r0 * COUT + c0g);
            float2 rv1 = *(const float2*)(res + (size_t)r1 * COUT + c0g);
            *(float2*)(outf + (size_t)r0 * COUT + c0g) = make_float2(acc[nt][0] + rv0.x, acc[nt][1] + rv0.y);
            *(float2*)(outf + (size_t)r1 * COUT + c0g) = make_float2(acc[nt][2] + rv1.x, acc[nt][3] + rv1.y);
        } else {
            #pragma unroll
            for (int i = 0; i < 4; i++)
                acc[nt][i] = 0.5f * acc[nt][i] * (1.0f + erff(acc[nt][i] * 0.70710678118654752f));
            outh[(size_t)r0 * (COUT / 2) + ntG * 4 + lj] = bfpack(acc[nt][0], acc[nt][1]);
            outh[(size_t)r1 * (COUT / 2) + ntG * 4 + lj] = bfpack(acc[nt][2], acc[nt][3]);
        }
    }
}

// ---------------- K/V pre-gather into fragment layout (pure word permutes) ----------------
__global__ void __launch_bounds__(384) kvprep_kernel() {
    int blk = blockIdx.x;
    int w = blk / NTILE, T = blk - w * NTILE;
    int wd = w / 9; int wr = w - wd * 9;
    int wh = wr / 3; int ww = wr - wh * 3;
    int tid = threadIdx.x;
    int isV = tid >= 192;
    int r = isV ? tid - 192 : tid;
    int j = r & 31, h = r >> 5;

    int kk = T * 32 + j;
    int kz = kk / 144; int r2 = kk - kz * 144;
    int ky = r2 / 12;  int kx = r2 - ky * 12;
    int gz = wd * 8 + kz - PADW, gy = wh * 8 + ky - PADW, gx = ww * 8 + kx - PADW;

    unsigned kw[8];
    if ((unsigned)gz < 24u && (unsigned)gy < 24u && (unsigned)gx < 24u) {
        const uint4* s = (const uint4*)(g_qkvh +
            (size_t)((gz * DSP + gy) * DSP + gx) * 144 + (isV ? 96 : 48) + h * 8);
        uint4 s0 = s[0], s1 = s[1];
        kw[0] = s0.x; kw[1] = s0.y; kw[2] = s0.z; kw[3] = s0.w;
        kw[4] = s1.x; kw[5] = s1.y; kw[6] = s1.z; kw[7] = s1.w;
    } else {
        #pragma unroll
        for (int i = 0; i < 8; i++) kw[i] = 0u;
    }

    size_t tilebase = ((size_t)(w * HEADS + h) * NTILE + T) * 256;
    if (!isV) {
        uint2* dst = (uint2*)(g_kf + tilebase);
        int nt = j >> 3, lgrp = 4 * (j & 7);
        #pragma unroll
        for (int d = 0; d < 4; d++)
            dst[nt * 32 + lgrp + d] = make_uint2(kw[d], kw[d + 4]);
    } else {
        // V: pair keys (even j, odd j). Word n of pair = {V[even][n], V[odd][n]}.
        unsigned* dst = g_vf + tilebase;
        int kc = j >> 4, k2 = j & 15;
        int slotj = (k2 >> 1) & 3, rh = k2 >> 3;
        int par = j & 1;
        #pragma unroll
        for (int i = 0; i < 8; i++) {
            unsigned p = __shfl_xor_sync(0xffffffffu, kw[i], 1);
            int n = 2 * i + par;
            unsigned word = par ? __byte_perm(p, kw[i], 0x7632)
                                : __byte_perm(kw[i], p, 0x5410);
            dst[((kc * 2 + (n >> 3)) * 32 + 4 * (n & 7) + slotj) * 2 + rh] = word;
        }
    }
}

// ---------------- attention: fixed-base softmax (m=0), barrier-free ----------------
__global__ void __launch_bounds__(128) attn_kernel() {
    int b   = blockIdx.x;                   // 0..1295
    int w   = b / 48;  int rem = b - w * 48;
    int h   = rem >> 3, qo = rem & 7;
    int wd  = w / 9;   int wr = w - wd * 9;
    int wh  = wr / 3;  int ww = wr - wh * 3;
    int tid = threadIdx.x;
    int lane = tid & 31, wp = tid >> 5;
    int lj = lane & 3, lr = lane >> 2;

    int qbase = qo * 64 + wp * 16;

    // ---- Q fragments: direct word loads (scale folded into Wq) + bias ptrs ----
    unsigned qfrag[4];
    const __nv_bfloat16* bp[2];
    int tqs[2];
    #pragma unroll
    for (int half = 0; half < 2; half++) {
        int qw = qbase + 8 * half + lr;
        int z = qw >> 6, y = (qw >> 3) & 7, xx = qw & 7;
        int tq = ((wd * 8 + z) * DSP + (wh * 8 + y)) * DSP + (ww * 8 + xx);
        tqs[half] = tq;
        const unsigned* qp = g_qkvh + (size_t)tq * 144 + h * 8 + lj;
        qfrag[half]     = qp[0];
        qfrag[2 + half] = qp[4];
        bp[half] = g_bias + ((size_t)(h * QW3) + qw) * KW3 + 2 * lj;
    }

    const uint2* kG = (const uint2*)g_kf + ((size_t)(w * HEADS + h) * NTILE) * 128 + lane;
    const uint2* vG = (const uint2*)g_vf + ((size_t)(w * HEADS + h) * NTILE) * 128 + lane;

    float O[2][4];
    #pragma unroll
    for (int nt = 0; nt < 2; nt++)
        #pragma unroll
        for (int c = 0; c < 4; c++) O[nt][c] = 0.0f;
    float l[2] = { 0.0f, 0.0f };

    uint2 kb[4], vb[4], kbn[4], vbn[4];
    unsigned bb[2][4], bbn[2][4];
    #pragma unroll
    for (int nt = 0; nt < 4; nt++) { kb[nt] = kG[nt * 32]; vb[nt] = vG[nt * 32]; }
    #pragma unroll
    for (int half = 0; half < 2; half++)
        #pragma unroll
        for (int nt = 0; nt < 4; nt++)
            bb[half][nt] = *(const unsigned*)(bp[half] + nt * 8);

    #pragma unroll 2
    for (int t = 0; t < NTILE; t++) {
        if (t + 1 < NTILE) {
            const uint2* kN = kG + (t + 1) * 128;
            const uint2* vN = vG + (t + 1) * 128;
            #pragma unroll
            for (int nt = 0; nt < 4; nt++) { kbn[nt] = kN[nt * 32]; vbn[nt] = vN[nt * 32]; }
            #pragma unroll
            for (int half = 0; half < 2; half++)
                #pragma unroll
                for (int nt = 0; nt < 4; nt++)
                    bbn[half][nt] = *(const unsigned*)(bp[half] + (t + 1) * 32 + nt * 8);
        }

        // ---- S = bias (ALU shift-unpack, not cvt); S += Q K^T ----
        float S[4][4];
        #pragma unroll
        for (int nt = 0; nt < 4; nt++) {
            #pragma unroll
            for (int half = 0; half < 2; half++)
                bf2x_unpack(bb[half][nt], S[nt][2 * half], S[nt][2 * half + 1]);
        }
        #pragma unroll
        for (int nt = 0; nt < 4; nt++)
            mma16816(S[nt], qfrag, kb[nt].x, kb[nt].y);

        // ---- p = exp2(s), fixed base ----
        unsigned pfrag[2][4];
        #pragma unroll
        for (int half = 0; half < 2; half++) {
            int c0 = 2 * half;
            float ls = 0.0f;
            #pragma unroll
            for (int nt = 0; nt < 4; nt++) {
                float p0 = ex2(S[nt][c0]);
                float p1 = ex2(S[nt][c0 + 1]);
                ls += p0 + p1;
                S[nt][c0] = p0; S[nt][c0 + 1] = p1;
            }
            l[half] += ls;
        }
        #pragma unroll
        for (int kc = 0; kc < 2; kc++) {
            pfrag[kc][0] = bfpack(S[2 * kc][0],     S[2 * kc][1]);
            pfrag[kc][1] = bfpack(S[2 * kc][2],     S[2 * kc][3]);
            pfrag[kc][2] = bfpack(S[2 * kc + 1][0], S[2 * kc + 1][1]);
            pfrag[kc][3] = bfpack(S[2 * kc + 1][2], S[2 * kc + 1][3]);
        }

        // ---- O += P V ----
        #pragma unroll
        for (int kc = 0; kc < 2; kc++)
            #pragma unroll
            for (int nt = 0; nt < 2; nt++)
                mma16816(O[nt], pfrag[kc], vb[kc * 2 + nt].x, vb[kc * 2 + nt].y);

        #pragma unroll
        for (int nt = 0; nt < 4; nt++) { kb[nt] = kbn[nt]; vb[nt] = vbn[nt]; }
        #pragma unroll
        for (int half = 0; half < 2; half++)
            #pragma unroll
            for (int nt = 0; nt < 4; nt++) bb[half][nt] = bbn[half][nt];
    }

    // ---- finalize: quad row-sum, normalize, write bf16 ----
    #pragma unroll
    for (int half = 0; half < 2; half++) {
        float ls = l[half];
        ls += __shfl_xor_sync(0xffffffffu, ls, 1);
        ls += __shfl_xor_sync(0xffffffffu, ls, 2);
        float inv = 1.0f / ls;
        int c0 = 2 * half;
        unsigned* row = g_attnh + (size_t)tqs[half] * 48 + h * 8 + lj;
        row[0] = bfpack(O[0][c0] * inv, O[0][c0 + 1] * inv);
        row[4] = bfpack(O[1][c0] * inv, O[1][c0 + 1] * inv);
    }
}

// ---------------- launch ----------------
extern "C" void kernel_launch(void* const* d_in, const int* in_sizes, int n_in,
                              void* d_out, int out_size) {
    const float* x      = (const float*)d_in[0];
    const float* ln1_w  = (const float*)d_in[1];
    const float* ln1_b  = (const float*)d_in[2];
    const float* qkv_w  = (const float*)d_in[3];
    const float* qkv_b  = (const float*)d_in[4];
    const float* rpb    = (const float*)d_in[5];
    const float* proj_w = (const float*)d_in[6];
    const float* proj_b = (const float*)d_in[7];
    const float* ln2_w  = (const float*)d_in[8];
    const float* ln2_b  = (const float*)d_in[9];
    const float* fc1_w  = (const float*)d_in[10];
    const float* fc1_b  = (const float*)d_in[11];
    const float* fc2_w  = (const float*)d_in[12];
    const float* fc2_b  = (const float*)d_in[13];
    const int*   rpi    = (const int*)  d_in[14];
    float* out = (float*)d_out;

    unsigned *xnh, *qkvh, *attnh, *x2nh, *h1h;
    unsigned *wqkv, *wproj, *wfc1, *wfc2;
    float* x2;
    cudaGetSymbolAddress((void**)&xnh,   g_xnh);
    cudaGetSymbolAddress((void**)&qkvh,  g_qkvh);
    cudaGetSymbolAddress((void**)&attnh, g_attnh);
    cudaGetSymbolAddress((void**)&x2nh,  g_x2nh);
    cudaGetSymbolAddress((void**)&h1h,   g_h1h);
    cudaGetSymbolAddress((void**)&x2,    g_x2);
    cudaGetSymbolAddress((void**)&wqkv,  g_wqkv);
    cudaGetSymbolAddress((void**)&wproj, g_wproj);
    cudaGetSymbolAddress((void**)&wfc1,  g_wfc1);
    cudaGetSymbolAddress((void**)&wfc2,  g_wfc2);

    prep_kernel<<<144 + (QW3 * KW3 + 255) / 256, 256>>>(qkv_w, proj_w, fc1_w, fc2_w, rpi, rpb);

    ln_kernel<<<NTOK / 8, 256>>>(x, ln1_w, ln1_b, (__nv_bfloat16*)xnh);
    mma_gemm<96, 4, 0, true><<<dim3(NTOK / 64, 9), 128>>>(xnh, wqkv, qkv_b, nullptr, nullptr, qkvh, 288);

    kvprep_kernel<<<NWIN * NTILE, 384>>>();
    attn_kernel<<<NBLK2, 128>>>();

    mma_gemm<96, 2, 1, false><<<dim3(NTOK / 64, 6), 128>>>(attnh, wproj, proj_b, x, x2, nullptr, 96);
    ln_kernel<<<NTOK / 8, 256>>>(x2, ln2_w, ln2_b, (__nv_bfloat16*)x2nh);
    mma_gemm<96, 4, 2, false><<<dim3(NTOK / 64, 6), 128>>>(x2nh, wfc1, fc1_b, nullptr, nullptr, h1h, 192);
    mma_gemm<192, 2, 1, false><<<dim3(NTOK / 64, 6), 128>>>(h1h, wfc2, fc2_b, x2, out, nullptr, 96);
}